// round 13
// baseline (speedup 1.0000x reference)
#include <cuda_runtime.h>
#include <cuda_bf16.h>
#include <math.h>
#include <stdint.h>

// Problem constants
#define BB   16
#define SS   1024
#define EE   256
#define HH   256
#define G4H  1024
#define WT   256
#define MM   (BB * SS)

// ---------------------------------------------------------------------------
// Scratch
// ---------------------------------------------------------------------------
__device__ float g_pre_f[MM * G4H];
__device__ float g_pre_b[MM * G4H];
__device__ float g_pre_d[MM * G4H];
__device__ float g_hn[MM * HH];
__device__ float g_hb[MM * HH];
__device__ float g_dh[MM * HH];
__device__ float g_q [MM * WT];
__device__ float g_p [MM * WT];
__device__ float g_hx[2 * BB * HH];       // double-buffered h exchange (L2)
__device__ unsigned g_bar[3 * BB * 32];   // per-(launch,batch) counters, 128B apart

// ---------------------------------------------------------------------------
// f32x2 packed FMA helpers (GEMM)
// ---------------------------------------------------------------------------
typedef unsigned long long u64t;
__device__ __forceinline__ u64t pack2(float lo, float hi) {
    u64t r; asm("mov.b64 %0, {%1,%2};" : "=l"(r) : "f"(lo), "f"(hi)); return r;
}
__device__ __forceinline__ void unpack2(float& lo, float& hi, u64t v) {
    asm("mov.b64 {%0,%1}, %2;" : "=f"(lo), "=f"(hi) : "l"(v));
}
__device__ __forceinline__ void fma2(u64t& d, u64t a, u64t b) {
    asm("fma.rn.f32x2 %0, %1, %2, %0;" : "+l"(d) : "l"(a), "l"(b));
}

// fast activations (err ~1e-6; safe for downstream argmax)
__device__ __forceinline__ float sigm_fast(float x) {
    return __fdividef(1.0f, 1.0f + __expf(-x));
}
__device__ __forceinline__ float tanh_fast(float x) {
    return 1.0f - __fdividef(2.0f, __expf(2.0f * x) + 1.0f);
}

// ---------------------------------------------------------------------------
// Barrier-counter init (first node of the graph; re-zeroes each replay)
// ---------------------------------------------------------------------------
__global__ void init_bar_kernel() {
    int i = blockIdx.x * blockDim.x + threadIdx.x;
    if (i < 3 * BB * 32) g_bar[i] = 0u;
}

// ---------------------------------------------------------------------------
// Tiled fp32 GEMM with packed f32x2 FMA (validated across rounds).
// C[M,N] (= or +=) A[M,K] @ Bw[K,N] (+ bias). shiftA: row m reads A[m-1],
// zeros at (m % SS)==0.
// ---------------------------------------------------------------------------
#define GBM 128
#define GBN 64
#define GBK 16

__global__ __launch_bounds__(256) void gemm_kernel(
    const float* __restrict__ A, const float* __restrict__ Bw,
    const float* __restrict__ bias, float* __restrict__ C,
    int N, int K, int shiftA, int accFlag)
{
    __shared__ __align__(16) float As[GBK][GBM + 4];
    __shared__ __align__(16) float Bs[GBK][GBN];
    const int bm  = blockIdx.y * GBM;
    const int bn  = blockIdx.x * GBN;
    const int tid = threadIdx.x;
    const int tx  = tid & 15;
    const int ty  = tid >> 4;

    u64t acc2[4][4];
#pragma unroll
    for (int i = 0; i < 4; i++)
#pragma unroll
        for (int j = 0; j < 4; j++) acc2[i][j] = pack2(0.f, 0.f);

    for (int k0 = 0; k0 < K; k0 += GBK) {
        {
            int kr = tid >> 4;
            int cq = tid & 15;
            float4 v = *(const float4*)(Bw + (size_t)(k0 + kr) * N + bn + cq * 4);
            *(float4*)(&Bs[kr][cq * 4]) = v;
        }
#pragma unroll
        for (int l = 0; l < 2; l++) {
            int f4 = tid + l * 256;
            int r  = f4 >> 2;
            int kq = f4 & 3;
            int gm = bm + r;
            float4 v;
            if (shiftA && ((gm & (SS - 1)) == 0)) {
                v = make_float4(0.f, 0.f, 0.f, 0.f);
            } else {
                v = *(const float4*)(A + (size_t)(gm - shiftA) * K + k0 + kq * 4);
            }
            As[kq * 4 + 0][r] = v.x;
            As[kq * 4 + 1][r] = v.y;
            As[kq * 4 + 2][r] = v.z;
            As[kq * 4 + 3][r] = v.w;
        }
        __syncthreads();
#pragma unroll
        for (int kk = 0; kk < GBK; kk++) {
            ulonglong2 A0 = *(const ulonglong2*)(&As[kk][ty * 8]);
            ulonglong2 A1 = *(const ulonglong2*)(&As[kk][ty * 8 + 4]);
            u64t ar[4] = {A0.x, A0.y, A1.x, A1.y};
            float4 bv = *(const float4*)(&Bs[kk][tx * 4]);
            u64t bd[4] = {pack2(bv.x, bv.x), pack2(bv.y, bv.y),
                          pack2(bv.z, bv.z), pack2(bv.w, bv.w)};
#pragma unroll
            for (int i = 0; i < 4; i++)
#pragma unroll
                for (int j = 0; j < 4; j++) fma2(acc2[i][j], ar[i], bd[j]);
        }
        __syncthreads();
    }

    float4 bias4 = make_float4(0.f, 0.f, 0.f, 0.f);
    if (!accFlag && bias) bias4 = *(const float4*)(bias + bn + tx * 4);
#pragma unroll
    for (int i = 0; i < 4; i++) {
        float r0[4], r1[4];
#pragma unroll
        for (int j = 0; j < 4; j++) unpack2(r0[j], r1[j], acc2[i][j]);
#pragma unroll
        for (int h = 0; h < 2; h++) {
            float* rv = h ? r1 : r0;
            int gm = bm + ty * 8 + i * 2 + h;
            float* crow = C + (size_t)gm * N + bn + tx * 4;
            float4 v = make_float4(rv[0], rv[1], rv[2], rv[3]);
            if (accFlag) {
                float4 old = *(const float4*)crow;
                v.x += old.x; v.y += old.y; v.z += old.z; v.w += old.w;
            } else {
                v.x += bias4.x; v.y += bias4.y; v.z += bias4.z; v.w += bias4.w;
            }
            *(float4*)crow = v;
        }
    }
}

// ---------------------------------------------------------------------------
// Persistent LSTM recurrence — R2 skeleton (no clusters, global-memory h
// exchange) with: per-batch 8-way barriers on private 128B lines, sound
// CG-style fencing (stores -> syncwarp -> lane0 fence+publish; reader spin ->
// fence -> syncthreads; fence cumulativity covers peer lanes' stores),
// fused warp-0 gate stage (2 syncs/step), pre prefetched a full step ahead,
// fast activations.
// 128 blocks = 16 batches x 8 slices, 512 threads (c=tid&127 z-col,
// kh=tid>>7 k-split of 4x64). Whh slice register-resident (64 f/thread).
// ---------------------------------------------------------------------------
__global__ __launch_bounds__(512, 1) void lstm_kernel(
    const float* __restrict__ pre,    // [B,S,4H]
    const float* __restrict__ Whh,    // [H,4H]
    float* __restrict__ hout,         // [B,S,H]
    const float* __restrict__ cinit,  // null, or [B,S,H]: c0 = cinit[b,S-1,:]
    int backward, int slot)
{
    const int blk   = blockIdx.x;
    const int batch = blk >> 3;
    const int slice = blk & 7;
    const int tid   = threadIdx.x;
    const int c     = tid & 127;
    const int kh    = tid >> 7;
    const int lid   = tid & 31;
    const int gcol  = ((c >> 5) << 8) + (slice << 5) + (c & 31); // gate*256+unit

    __shared__ float hs[HH];
    __shared__ float part[512];

    unsigned* barp = &g_bar[(slot * BB + batch) * 32];

    float w[64];
#pragma unroll
    for (int j = 0; j < 64; j++)
        w[j] = Whh[(size_t)(kh * 64 + j) * G4H + gcol];

    float cst = 0.f;
    float pv[4];
    if (tid < 32) {
        if (cinit)
            cst = cinit[((size_t)batch * SS + (SS - 1)) * HH + (slice << 5) + lid];
        int t0 = backward ? (SS - 1) : 0;
        const float* pr = pre + ((size_t)batch * SS + t0) * G4H + (slice << 5) + lid;
#pragma unroll
        for (int g = 0; g < 4; g++) pv[g] = __ldcs(pr + g * HH);
    }
    if (tid < HH) hs[tid] = 0.f;   // h0 = 0
    __syncthreads();

    for (int s = 0; s < SS; s++) {
        const int t = backward ? (SS - 1 - s) : s;

        // load current h into smem (s=0: zeros already there)
        if (s > 0 && tid < HH / 4) {
            const float4* hrd =
                (const float4*)(g_hx + (s & 1) * (BB * HH) + batch * HH);
            *(float4*)(&hs[tid * 4]) = __ldcg(hrd + tid);
        }
        __syncthreads();

        // matvec partial: 64 k per thread (warp-uniform smem broadcast reads)
        float a0 = 0.f, a1 = 0.f, a2 = 0.f, a3 = 0.f;
        const float* hp = &hs[kh * 64];
#pragma unroll
        for (int j4 = 0; j4 < 4; j4++) {
            float4 h0 = *(const float4*)(hp + j4 * 16);
            float4 h1 = *(const float4*)(hp + j4 * 16 + 4);
            float4 h2v = *(const float4*)(hp + j4 * 16 + 8);
            float4 h3 = *(const float4*)(hp + j4 * 16 + 12);
            const float* ww = w + j4 * 16;
            a0 = fmaf(h0.x, ww[0],  a0); a1 = fmaf(h0.y, ww[1],  a1);
            a2 = fmaf(h0.z, ww[2],  a2); a3 = fmaf(h0.w, ww[3],  a3);
            a0 = fmaf(h1.x, ww[4],  a0); a1 = fmaf(h1.y, ww[5],  a1);
            a2 = fmaf(h1.z, ww[6],  a2); a3 = fmaf(h1.w, ww[7],  a3);
            a0 = fmaf(h2v.x, ww[8],  a0); a1 = fmaf(h2v.y, ww[9],  a1);
            a2 = fmaf(h2v.z, ww[10], a2); a3 = fmaf(h2v.w, ww[11], a3);
            a0 = fmaf(h3.x, ww[12], a0); a1 = fmaf(h3.y, ww[13], a1);
            a2 = fmaf(h3.z, ww[14], a2); a3 = fmaf(h3.w, ww[15], a3);
        }
        part[tid] = (a0 + a1) + (a2 + a3);
        __syncthreads();

        if (tid < 32) {
            float z[4];
#pragma unroll
            for (int g = 0; g < 4; g++) {
                int pc = g * 32 + lid;
                z[g] = (part[pc] + part[128 + pc])
                     + (part[256 + pc] + part[384 + pc]) + pv[g];
            }
            // prefetch NEXT step's pre (consumed a full step later: hidden)
            if (s + 1 < SS) {
                int tn = backward ? (SS - 2 - s) : (s + 1);
                const float* pr =
                    pre + ((size_t)batch * SS + tn) * G4H + (slice << 5) + lid;
#pragma unroll
                for (int g = 0; g < 4; g++) pv[g] = __ldcs(pr + g * HH);
            }
            float c2 = sigm_fast(z[1]) * cst + sigm_fast(z[0]) * tanh_fast(z[2]);
            cst = c2;
            float h2 = sigm_fast(z[3]) * tanh_fast(c2);
            hout[((size_t)batch * SS + t) * HH + (slice << 5) + lid] = h2;
            if (s + 1 < SS) {
                // publish h for step s+1 straight to L2
                __stcg(&g_hx[((s + 1) & 1) * (BB * HH) + batch * HH
                             + (slice << 5) + lid], h2);
                __syncwarp();          // HB edge: all lanes' stores -> lane0
                if (lid == 0) {
                    __threadfence();   // B-cumulative release (covers peers)
                    atomicAdd(barp, 1u);
                    unsigned tgt = 8u * (unsigned)(s + 1);
                    while (*(volatile unsigned*)barp < tgt) __nanosleep(32);
                    __threadfence();   // A-cumulative acquire
                }
                __syncwarp();
            }
        }
        // block-wide propagation of warp0's acquire; protects part[]/hs reuse
        __syncthreads();
    }
}

// ---------------------------------------------------------------------------
// Pointer decisions (R2 version, proven rel_err 0.0; decide2 reverted)
// ---------------------------------------------------------------------------
__global__ __launch_bounds__(256) void decide_kernel(
    const float* __restrict__ q, const float* __restrict__ pm,
    const float* __restrict__ vt1, float* __restrict__ out)
{
    const int b   = blockIdx.x;
    const int tid = threadIdx.x;
    __shared__ float pv[WT];
    __shared__ float v1[WT];
    __shared__ float rvals[256];
    __shared__ int   ridx[256];
    __shared__ int   r_sh;

    v1[tid] = vt1[tid];
    for (int s = tid; s < SS; s += 256) out[s * BB + b] = 0.f;
    __syncthreads();

    int t = 0;
    while (true) {
        pv[tid] = pm[((size_t)b * SS + t) * WT + tid];
        __syncthreads();

        float bv = -1e30f;
        int   bj = SS;
        for (int j = t + tid; j < SS; j += 256) {
            const float* qr = q + ((size_t)b * SS + j) * WT;
            float sacc = 0.f;
            for (int wi = 0; wi < WT; wi += 4) {
                float4 qq = *(const float4*)(qr + wi);
                sacc += tanhf(qq.x + pv[wi + 0]) * v1[wi + 0];
                sacc += tanhf(qq.y + pv[wi + 1]) * v1[wi + 1];
                sacc += tanhf(qq.z + pv[wi + 2]) * v1[wi + 2];
                sacc += tanhf(qq.w + pv[wi + 3]) * v1[wi + 3];
            }
            if (sacc > bv) { bv = sacc; bj = j; }
        }
        rvals[tid] = bv;
        ridx[tid]  = bj;
        __syncthreads();

        if (tid == 0) {
            float best = rvals[0];
            int   bi   = ridx[0];
            for (int i = 1; i < 256; i++) {
                if (rvals[i] > best || (rvals[i] == best && ridx[i] < bi)) {
                    best = rvals[i]; bi = ridx[i];
                }
            }
            out[bi * BB + b] = 1.0f;
            r_sh = bi;
        }
        __syncthreads();
        int r = r_sh;
        if (r <= t) break;
        t = r;
    }
}

// ---------------------------------------------------------------------------
// Launch. My 4th launch is a BIG gemm so the ncu capture slot finally
// measures one (lstm captures are replay-broken).
// ---------------------------------------------------------------------------
extern "C" void kernel_launch(void* const* d_in, const int* in_sizes, int n_in,
                              void* d_out, int out_size) {
    const float* x        = (const float*)d_in[0];
    const float* eWih_f   = (const float*)d_in[1];
    const float* eWhh_f   = (const float*)d_in[2];
    const float* eb_f     = (const float*)d_in[3];
    const float* eWih_b   = (const float*)d_in[4];
    const float* eWhh_b   = (const float*)d_in[5];
    const float* eb_b     = (const float*)d_in[6];
    const float* dWih     = (const float*)d_in[7];
    const float* dWhh     = (const float*)d_in[8];
    const float* db       = (const float*)d_in[9];
    const float* W1       = (const float*)d_in[10];
    const float* W2       = (const float*)d_in[11];
    const float* W3       = (const float*)d_in[12];
    const float* W4       = (const float*)d_in[13];
    const float* vt1      = (const float*)d_in[14];
    float*       out      = (float*)d_out;

    float *pre_f, *pre_b, *pre_d, *hn, *hb, *dh, *q, *p;
    cudaGetSymbolAddress((void**)&pre_f, g_pre_f);
    cudaGetSymbolAddress((void**)&pre_b, g_pre_b);
    cudaGetSymbolAddress((void**)&pre_d, g_pre_d);
    cudaGetSymbolAddress((void**)&hn,    g_hn);
    cudaGetSymbolAddress((void**)&hb,    g_hb);
    cudaGetSymbolAddress((void**)&dh,    g_dh);
    cudaGetSymbolAddress((void**)&q,     g_q);
    cudaGetSymbolAddress((void**)&p,     g_p);

    dim3 thr(256);
    dim3 gridBig(G4H / GBN, MM / GBM);   // N=1024
    dim3 gridSml(WT / GBN, MM / GBM);    // N=256

    // 1: reset per-batch barrier counters (runs on every graph replay)
    init_bar_kernel<<<6, 256>>>();

    // 2-3: forward-encoder pre + one small gemm
    gemm_kernel<<<gridBig, thr>>>(x, eWih_f, eb_f, pre_f, G4H, EE, 0, 0);
    gemm_kernel<<<gridSml, thr>>>(x, W3, nullptr, p, WT, EE, 0, 0);

    // 4: BIG gemm (shifted-x part of decoder pre)  <-- ncu capture slot
    gemm_kernel<<<gridBig, thr>>>(x, dWih, db, pre_d, G4H, EE, 1, 0);

    // 5: backward-encoder pre
    gemm_kernel<<<gridBig, thr>>>(x, eWih_b, eb_b, pre_b, G4H, EE, 0, 0);

    // 6-7: encoder recurrences
    lstm_kernel<<<128, 512>>>(pre_f, eWhh_f, hn, nullptr, 0, 0);
    lstm_kernel<<<128, 512>>>(pre_b, eWhh_b, hb, nullptr, 1, 1);

    // 8-11: remaining projections
    gemm_kernel<<<gridSml, thr>>>(x, W2, nullptr, q, WT, EE, 0, 0);
    gemm_kernel<<<gridBig, thr>>>(hn, dWih + (size_t)EE * G4H, nullptr, pre_d, G4H, HH, 1, 1);
    gemm_kernel<<<gridSml, thr>>>(hn, W1, nullptr, q, WT, HH, 0, 1);
    gemm_kernel<<<gridSml, thr>>>(hb, W1 + (size_t)HH * WT, nullptr, q, WT, HH, 0, 1);

    // 12-13: decoder recurrence + final projection
    lstm_kernel<<<128, 512>>>(pre_d, dWhh, dh, hn, 0, 2);
    gemm_kernel<<<gridSml, thr>>>(dh, W4, nullptr, p, WT, HH, 0, 1);

    // 14: decisions
    decide_kernel<<<BB, 256>>>(q, p, vt1, out);
}

// round 15
// speedup vs baseline: 1.5298x; 1.5298x over previous
#include <cuda_runtime.h>
#include <cuda_bf16.h>
#include <math.h>

// Problem constants
#define BB   16
#define SS   1024
#define EE   256
#define HH   256
#define G4H  1024
#define WT   256
#define MM   (BB * SS)

// ---------------------------------------------------------------------------
// Scratch (device globals; allocation-free per harness rules)
// ---------------------------------------------------------------------------
__device__ float g_pre_f[MM * G4H];   // x@Wih_f + b_f
__device__ float g_pre_b[MM * G4H];   // x@Wih_b + b_b
__device__ float g_pre_d[MM * G4H];   // shifted [x,hn]@dec_Wih + dec_b
__device__ float g_hn[MM * HH];       // fwd encoder hiddens
__device__ float g_hb[MM * HH];       // bwd encoder hiddens
__device__ float g_dh[MM * HH];       // decoder hiddens
__device__ float g_q [MM * WT];       // hn@W1a + hb@W1b + x@W2   (per-position j)
__device__ float g_p [MM * WT];       // x@W3 + dh@W4             (per-step t)
__device__ float g_hcur[2 * BB * HH]; // double-buffered current h
__device__ unsigned g_bar_cnt;        // monotonic grid-barrier counter

// ---------------------------------------------------------------------------
// Monotonic grid barrier (all blocks co-resident; no reset needed)
// ---------------------------------------------------------------------------
__device__ __forceinline__ void grid_barrier(unsigned nb) {
    __syncthreads();
    if (threadIdx.x == 0) {
        __threadfence();
        unsigned a = atomicAdd(&g_bar_cnt, 1u);
        unsigned target = a - (a % nb) + nb;
        while (*(volatile unsigned*)&g_bar_cnt < target) __nanosleep(64);
    }
    __syncthreads();
}

// ---------------------------------------------------------------------------
// Tiled fp32 GEMM: C[M,N] (= or +=) A[M,K] @ Bw[K,N] (+ bias on first pass)
// shiftA: logical row m reads A[m-1]; rows with (m % SS)==0 read zeros.
// (VERBATIM from the 8650us baseline)
// ---------------------------------------------------------------------------
#define GBM 128
#define GBN 64
#define GBK 16

__global__ __launch_bounds__(256) void gemm_kernel(
    const float* __restrict__ A, const float* __restrict__ Bw,
    const float* __restrict__ bias, float* __restrict__ C,
    int N, int K, int shiftA, int accFlag)
{
    __shared__ __align__(16) float As[GBK][GBM + 4];
    __shared__ __align__(16) float Bs[GBK][GBN];
    const int bm  = blockIdx.y * GBM;
    const int bn  = blockIdx.x * GBN;
    const int tid = threadIdx.x;
    const int tx  = tid & 15;   // n-subtile (4 cols)
    const int ty  = tid >> 4;   // m-subtile (8 rows)

    float acc[8][4];
#pragma unroll
    for (int i = 0; i < 8; i++)
#pragma unroll
        for (int j = 0; j < 4; j++) acc[i][j] = 0.f;

    for (int k0 = 0; k0 < K; k0 += GBK) {
        {
            int kr = tid >> 4;
            int cq = tid & 15;
            float4 v = *(const float4*)(Bw + (size_t)(k0 + kr) * N + bn + cq * 4);
            *(float4*)(&Bs[kr][cq * 4]) = v;
        }
#pragma unroll
        for (int l = 0; l < 2; l++) {
            int f4 = tid + l * 256;
            int r  = f4 >> 2;        // 0..127
            int kq = f4 & 3;         // which float4 in k
            int gm = bm + r;
            float4 v;
            if (shiftA && ((gm & (SS - 1)) == 0)) {
                v = make_float4(0.f, 0.f, 0.f, 0.f);
            } else {
                v = *(const float4*)(A + (size_t)(gm - shiftA) * K + k0 + kq * 4);
            }
            As[kq * 4 + 0][r] = v.x;
            As[kq * 4 + 1][r] = v.y;
            As[kq * 4 + 2][r] = v.z;
            As[kq * 4 + 3][r] = v.w;
        }
        __syncthreads();
#pragma unroll
        for (int kk = 0; kk < GBK; kk++) {
            float4 a0 = *(const float4*)(&As[kk][ty * 8]);
            float4 a1 = *(const float4*)(&As[kk][ty * 8 + 4]);
            float4 bv = *(const float4*)(&Bs[kk][tx * 4]);
            float am[8] = {a0.x, a0.y, a0.z, a0.w, a1.x, a1.y, a1.z, a1.w};
            float bmv[4] = {bv.x, bv.y, bv.z, bv.w};
#pragma unroll
            for (int i = 0; i < 8; i++)
#pragma unroll
                for (int j = 0; j < 4; j++) acc[i][j] += am[i] * bmv[j];
        }
        __syncthreads();
    }

    float4 bias4 = make_float4(0.f, 0.f, 0.f, 0.f);
    if (!accFlag && bias) bias4 = *(const float4*)(bias + bn + tx * 4);
#pragma unroll
    for (int i = 0; i < 8; i++) {
        int gm = bm + ty * 8 + i;
        float* crow = C + (size_t)gm * N + bn + tx * 4;
        float4 v = make_float4(acc[i][0], acc[i][1], acc[i][2], acc[i][3]);
        if (accFlag) {
            float4 old = *(const float4*)crow;
            v.x += old.x; v.y += old.y; v.z += old.z; v.w += old.w;
        } else {
            v.x += bias4.x; v.y += bias4.y; v.z += bias4.z; v.w += bias4.w;
        }
        *(float4*)crow = v;
    }
}

// ---------------------------------------------------------------------------
// Persistent LSTM recurrence (VERBATIM from the 8650us baseline).
// 128 blocks = 16 batches x 8 unit-slices, 512 threads.
// ---------------------------------------------------------------------------
__device__ __forceinline__ float sigm(float x) {
    return 1.0f / (1.0f + expf(-x));
}

__global__ __launch_bounds__(512, 1) void lstm_kernel(
    const float* __restrict__ pre,    // [B,S,4H]
    const float* __restrict__ Whh,    // [H,4H]
    float* __restrict__ hout,         // [B,S,H]
    const float* __restrict__ cinit,  // null, or [B,S,H]: c0 = cinit[b,S-1,:]
    int backward)
{
    const int blk   = blockIdx.x;      // 0..127
    const int batch = blk >> 3;
    const int slice = blk & 7;
    const int tid   = threadIdx.x;
    const int c     = tid & 127;
    const int kh    = tid >> 7;
    const int gcol  = ((c >> 5) << 8) + (slice << 5) + (c & 31); // gate*256 + unit

    __shared__ float hs[HH];
    __shared__ float part[512];
    __shared__ float zs[128];

    // register-resident Whh slice
    float w[64];
#pragma unroll
    for (int j = 0; j < 64; j++)
        w[j] = Whh[(size_t)(kh * 64 + j) * G4H + gcol];

    // cell state (threads 0..31 own one unit each)
    float cst = 0.f;
    if (tid < 32 && cinit)
        cst = cinit[((size_t)batch * SS + (SS - 1)) * HH + (slice << 5) + tid];

    // zero h buffer 0 for this batch
    if (tid < HH) g_hcur[batch * HH + tid] = 0.f;
    __threadfence();
    grid_barrier(gridDim.x);

    for (int s = 0; s < SS; s++) {
        const int t = backward ? (SS - 1 - s) : s;

        // prefetch pre-activation (DRAM) — consumed after the matvec
        float preval = 0.f;
        if (tid < 128)
            preval = pre[((size_t)batch * SS + t) * G4H + gcol];

        // load h (L2, bypass L1) into smem
        const float4* hrd = (const float4*)(g_hcur + (s & 1) * (BB * HH) + batch * HH);
        if (tid < HH / 4)
            *(float4*)(&hs[tid * 4]) = __ldcg(hrd + tid);
        __syncthreads();

        // matvec partial: 64 k per thread
        float acc = 0.f;
        const float* hp = hs + kh * 64;
#pragma unroll
        for (int j4 = 0; j4 < 16; j4++) {
            float4 hv = *(const float4*)(hp + j4 * 4);
            acc += hv.x * w[j4 * 4 + 0];
            acc += hv.y * w[j4 * 4 + 1];
            acc += hv.z * w[j4 * 4 + 2];
            acc += hv.w * w[j4 * 4 + 3];
        }
        part[(kh << 7) + c] = acc;
        __syncthreads();

        if (tid < 128)
            zs[tid] = part[tid] + part[128 + tid] + part[256 + tid] + part[384 + tid] + preval;
        __syncthreads();

        if (tid < 32) {
            float zi = zs[tid], zf = zs[32 + tid], zg = zs[64 + tid], zo = zs[96 + tid];
            float c2 = sigm(zf) * cst + sigm(zi) * tanhf(zg);
            cst = c2;
            float h2 = sigm(zo) * tanhf(c2);
            int ucol = (slice << 5) + tid;
            g_hcur[((s & 1) ^ 1) * (BB * HH) + batch * HH + ucol] = h2;
            hout[((size_t)batch * SS + t) * HH + ucol] = h2;
        }
        __threadfence();
        grid_barrier(gridDim.x);
    }
}

// ---------------------------------------------------------------------------
// Pointer decisions (VERBATIM from the 8650us baseline)
// ---------------------------------------------------------------------------
__global__ __launch_bounds__(256) void decide_kernel(
    const float* __restrict__ q,    // [B,S,WT]
    const float* __restrict__ pm,   // [B,S,WT]
    const float* __restrict__ vt1,  // [WT]
    float* __restrict__ out)        // [S,B]
{
    const int b   = blockIdx.x;
    const int tid = threadIdx.x;
    __shared__ float pv[WT];
    __shared__ float v1[WT];
    __shared__ float rvals[256];
    __shared__ int   ridx[256];
    __shared__ int   r_sh;

    v1[tid] = vt1[tid];
    for (int s = tid; s < SS; s += 256) out[s * BB + b] = 0.f;
    __syncthreads();

    int t = 0;
    while (true) {
        pv[tid] = pm[((size_t)b * SS + t) * WT + tid];
        __syncthreads();

        float bv = -1e30f;
        int   bj = SS;
        for (int j = t + tid; j < SS; j += 256) {
            const float* qr = q + ((size_t)b * SS + j) * WT;
            float sacc = 0.f;
            for (int wi = 0; wi < WT; wi += 4) {
                float4 qq = *(const float4*)(qr + wi);
                sacc += tanhf(qq.x + pv[wi + 0]) * v1[wi + 0];
                sacc += tanhf(qq.y + pv[wi + 1]) * v1[wi + 1];
                sacc += tanhf(qq.z + pv[wi + 2]) * v1[wi + 2];
                sacc += tanhf(qq.w + pv[wi + 3]) * v1[wi + 3];
            }
            if (sacc > bv) { bv = sacc; bj = j; }   // j ascending -> first max
        }
        rvals[tid] = bv;
        ridx[tid]  = bj;
        __syncthreads();

        if (tid == 0) {
            float best = rvals[0];
            int   bi   = ridx[0];
            for (int i = 1; i < 256; i++) {
                if (rvals[i] > best || (rvals[i] == best && ridx[i] < bi)) {
                    best = rvals[i]; bi = ridx[i];
                }
            }
            out[bi * BB + b] = 1.0f;
            r_sh = bi;
        }
        __syncthreads();
        int r = r_sh;
        if (r <= t) break;   // r == t ends the chain
        t = r;
    }
}

// ---------------------------------------------------------------------------
// Launch: same kernels as the 8650us baseline, but as a multi-stream DAG.
// s0 (default): pre_f -> fwd -> bwd -> dec -> W4 -> decide  (lstms serialized
//   on s0 -> g_hcur / g_bar_cnt sharing stays exactly as validated)
// s1: pre_b                         (hidden under pre_f + fwd)
// s2: W2, W3, pre_d-x               (hidden under fwd)
//     then [after fwd] pre_d-hn, W1-hn   (hidden under bwd)
//     then [after bwd] W1-hb             (hidden under dec)
// Accumulation chains (q: W2->W1hn->W1hb; pre_d: x->hn) stay stream-ordered
// on s2. Streams/events are created once on the correctness call (outside
// graph capture); the captured work is identical on every call.
// ---------------------------------------------------------------------------
extern "C" void kernel_launch(void* const* d_in, const int* in_sizes, int n_in,
                              void* d_out, int out_size) {
    const float* x        = (const float*)d_in[0];
    const float* eWih_f   = (const float*)d_in[1];
    const float* eWhh_f   = (const float*)d_in[2];
    const float* eb_f     = (const float*)d_in[3];
    const float* eWih_b   = (const float*)d_in[4];
    const float* eWhh_b   = (const float*)d_in[5];
    const float* eb_b     = (const float*)d_in[6];
    const float* dWih     = (const float*)d_in[7];
    const float* dWhh     = (const float*)d_in[8];
    const float* db       = (const float*)d_in[9];
    const float* W1       = (const float*)d_in[10];
    const float* W2       = (const float*)d_in[11];
    const float* W3       = (const float*)d_in[12];
    const float* W4       = (const float*)d_in[13];
    const float* vt1      = (const float*)d_in[14];
    float*       out      = (float*)d_out;

    float *pre_f, *pre_b, *pre_d, *hn, *hb, *dh, *q, *p;
    cudaGetSymbolAddress((void**)&pre_f, g_pre_f);
    cudaGetSymbolAddress((void**)&pre_b, g_pre_b);
    cudaGetSymbolAddress((void**)&pre_d, g_pre_d);
    cudaGetSymbolAddress((void**)&hn,    g_hn);
    cudaGetSymbolAddress((void**)&hb,    g_hb);
    cudaGetSymbolAddress((void**)&dh,    g_dh);
    cudaGetSymbolAddress((void**)&q,     g_q);
    cudaGetSymbolAddress((void**)&p,     g_p);

    // one-time stream/event setup (correctness call runs before capture)
    static cudaStream_t s1 = nullptr, s2 = nullptr;
    static cudaEvent_t  e0, e_preb, e_fwd, e_bwd, e_pdhn, e_q;
    if (s1 == nullptr) {
        cudaStreamCreateWithFlags(&s1, cudaStreamNonBlocking);
        cudaStreamCreateWithFlags(&s2, cudaStreamNonBlocking);
        cudaEventCreateWithFlags(&e0,     cudaEventDisableTiming);
        cudaEventCreateWithFlags(&e_preb, cudaEventDisableTiming);
        cudaEventCreateWithFlags(&e_fwd,  cudaEventDisableTiming);
        cudaEventCreateWithFlags(&e_bwd,  cudaEventDisableTiming);
        cudaEventCreateWithFlags(&e_pdhn, cudaEventDisableTiming);
        cudaEventCreateWithFlags(&e_q,    cudaEventDisableTiming);
    }

    dim3 thr(256);
    dim3 gridBig(G4H / GBN, MM / GBM);   // N=1024
    dim3 gridSml(WT / GBN, MM / GBM);    // N=256

    // fork
    cudaEventRecord(e0, 0);
    cudaStreamWaitEvent(s1, e0, 0);
    cudaStreamWaitEvent(s2, e0, 0);

    // s1: backward-encoder pre (only gate for bwd lstm)
    gemm_kernel<<<gridBig, thr, 0, s1>>>(x, eWih_b, eb_b, pre_b, G4H, EE, 0, 0);
    cudaEventRecord(e_preb, s1);

    // s2: x-only projections (hidden under fwd lstm)
    gemm_kernel<<<gridSml, thr, 0, s2>>>(x, W2, nullptr, q, WT, EE, 0, 0);
    gemm_kernel<<<gridSml, thr, 0, s2>>>(x, W3, nullptr, p, WT, EE, 0, 0);
    gemm_kernel<<<gridBig, thr, 0, s2>>>(x, dWih, db, pre_d, G4H, EE, 1, 0);

    // s0: fwd-encoder pre + fwd recurrence
    gemm_kernel<<<gridBig, thr>>>(x, eWih_f, eb_f, pre_f, G4H, EE, 0, 0);
    lstm_kernel<<<128, 512>>>(pre_f, eWhh_f, hn, nullptr, 0);
    cudaEventRecord(e_fwd, 0);

    // s2: hn-dependent projections (hidden under bwd lstm)
    cudaStreamWaitEvent(s2, e_fwd, 0);
    gemm_kernel<<<gridBig, thr, 0, s2>>>(hn, dWih + (size_t)EE * G4H, nullptr,
                                         pre_d, G4H, HH, 1, 1);
    cudaEventRecord(e_pdhn, s2);
    gemm_kernel<<<gridSml, thr, 0, s2>>>(hn, W1, nullptr, q, WT, HH, 0, 1);

    // s0: bwd recurrence
    cudaStreamWaitEvent(0, e_preb, 0);
    lstm_kernel<<<128, 512>>>(pre_b, eWhh_b, hb, nullptr, 1);
    cudaEventRecord(e_bwd, 0);

    // s2: hb-dependent projection (hidden under decoder lstm)
    cudaStreamWaitEvent(s2, e_bwd, 0);
    gemm_kernel<<<gridSml, thr, 0, s2>>>(hb, W1 + (size_t)HH * WT, nullptr,
                                         q, WT, HH, 0, 1);
    cudaEventRecord(e_q, s2);

    // s0: decoder recurrence (pre_d complete via e_pdhn; c0 = hn[:,S-1,:])
    cudaStreamWaitEvent(0, e_pdhn, 0);
    lstm_kernel<<<128, 512>>>(pre_d, dWhh, dh, hn, 0);

    // s0: final projection (W3 done before e_pdhn by s2 stream order) + join
    gemm_kernel<<<gridSml, thr>>>(dh, W4, nullptr, p, WT, HH, 0, 1);
    cudaStreamWaitEvent(0, e_q, 0);

    // decisions
    decide_kernel<<<BB, 256>>>(q, p, vt1, out);
}